// round 5
// baseline (speedup 1.0000x reference)
#include <cuda_runtime.h>
#include <math.h>

#define T_TOK 2048
#define H_DIM 1024
#define I_DIM 2048
#define E_NUM 16
#define PAIRS (T_TOK * 2)

// ---------------- scratch (device globals; no allocations) ----------------
__device__ int   g_cnt[E_NUM];
__device__ int   g_off[E_NUM + 1];
__device__ int   g_btok[E_NUM * T_TOK];
__device__ float g_bw[E_NUM * T_TOK];
__device__ int   g_ptok[PAIRS];
__device__ float g_pw[PAIRS];
__device__ float g_gate[(size_t)PAIRS * I_DIM];   // later holds hidden = silu(g)*u*w
__device__ float g_up[(size_t)PAIRS * I_DIM];

// ---------------- kernel 1: zero output + counts ----------------
__global__ void k_zero(float* out) {
    int stride = gridDim.x * blockDim.x;
    for (int i = blockIdx.x * blockDim.x + threadIdx.x; i < T_TOK * H_DIM; i += stride)
        out[i] = 0.0f;
    if (blockIdx.x == 0 && threadIdx.x < E_NUM) g_cnt[threadIdx.x] = 0;
}

// ---------------- kernel 2: router (warp per token) ----------------
__global__ void k_router(const float* __restrict__ x, const float* __restrict__ wr) {
    int warp = (blockIdx.x * blockDim.x + threadIdx.x) >> 5;
    int lane = threadIdx.x & 31;
    if (warp >= T_TOK) return;
    const float* xr = x + (size_t)warp * H_DIM;

    float acc[E_NUM];
#pragma unroll
    for (int e = 0; e < E_NUM; e++) acc[e] = 0.0f;

    for (int h = lane; h < H_DIM; h += 32) {
        float xv = xr[h];
        const float4* w4 = (const float4*)(wr + (size_t)h * E_NUM);
#pragma unroll
        for (int q = 0; q < 4; q++) {
            float4 w = w4[q];
            acc[q * 4 + 0] += xv * w.x;
            acc[q * 4 + 1] += xv * w.y;
            acc[q * 4 + 2] += xv * w.z;
            acc[q * 4 + 3] += xv * w.w;
        }
    }
#pragma unroll
    for (int e = 0; e < E_NUM; e++) {
#pragma unroll
        for (int o = 16; o > 0; o >>= 1)
            acc[e] += __shfl_xor_sync(0xffffffffu, acc[e], o);
    }
    if (lane == 0) {
        float best = -1e30f, sec = -1e30f;
        int be = 0, se = 0;
#pragma unroll
        for (int e = 0; e < E_NUM; e++) {
            float v = acc[e];
            if (v > best) { sec = best; se = be; best = v; be = e; }
            else if (v > sec) { sec = v; se = e; }
        }
        // softmax denominator cancels when renormalizing over top-2
        float w0 = 1.0f / (1.0f + expf(sec - best));
        float w1 = 1.0f - w0;
        int p0 = atomicAdd(&g_cnt[be], 1);
        g_btok[be * T_TOK + p0] = warp;
        g_bw[be * T_TOK + p0] = w0;
        int p1 = atomicAdd(&g_cnt[se], 1);
        g_btok[se * T_TOK + p1] = warp;
        g_bw[se * T_TOK + p1] = w1;
    }
}

// ---------------- kernel 3: offsets (tiny scan over 16) ----------------
__global__ void k_off() {
    if (threadIdx.x == 0) {
        int s = 0;
        for (int e = 0; e < E_NUM; e++) { g_off[e] = s; s += g_cnt[e]; }
        g_off[E_NUM] = s;
    }
}

// ---------------- kernel 4: compact pair arrays ----------------
__global__ void k_pairs() {
    int e = blockIdx.x;
    int n = g_cnt[e], o = g_off[e];
    for (int p = threadIdx.x; p < n; p += blockDim.x) {
        g_ptok[o + p] = g_btok[e * T_TOK + p];
        g_pw[o + p]   = g_bw[e * T_TOK + p];
    }
}

// ---------------- kernel 5/6: gather SGEMM  C[row, n] = x[tok(row), :] @ W[e]
// block tile 128x128, K-tile 8, 256 threads, 8x8 microtile, double-buffered smem
__global__ __launch_bounds__(256, 2) void k_gemm1(const float* __restrict__ x,
                                                  const float* __restrict__ Wall,
                                                  int which /*0=gate,1=up*/) {
    const int e = blockIdx.z;
    const int ne = g_cnt[e];
    const int m0 = blockIdx.y * 128;
    if (m0 >= ne) return;
    const int n0 = blockIdx.x * 128;
    const int off = g_off[e];
    const float* B = Wall + (size_t)e * H_DIM * I_DIM;   // [H, I]
    float* C = which ? g_up : g_gate;

    __shared__ float As[2][8][132];
    __shared__ float Bs[2][8][128];

    const int tid = threadIdx.x;
    const int tx = tid & 15, ty = tid >> 4;

    const int arow = tid >> 1;
    const int acol = (tid & 1) * 4;
    const int m = m0 + arow;
    const bool avalid = (m < ne);
    const float* aptr = avalid ? (x + (size_t)g_ptok[off + m] * H_DIM + acol) : x;

    const int bk = tid >> 5;
    const int bn = (tid & 31) * 4;
    const float* bptr = B + (size_t)bk * I_DIM + n0 + bn;

    float4 aR = avalid ? *(const float4*)aptr : make_float4(0, 0, 0, 0);
    float4 bR = *(const float4*)bptr;

    float acc[8][8];
#pragma unroll
    for (int i = 0; i < 8; i++)
#pragma unroll
        for (int j = 0; j < 8; j++) acc[i][j] = 0.0f;

    int buf = 0;
    As[0][acol + 0][arow] = aR.x; As[0][acol + 1][arow] = aR.y;
    As[0][acol + 2][arow] = aR.z; As[0][acol + 3][arow] = aR.w;
    *(float4*)&Bs[0][bk][bn] = bR;
    __syncthreads();

    const int KT = H_DIM / 8;
    for (int kt = 0; kt < KT; kt++) {
        if (kt + 1 < KT) {
            int ko = (kt + 1) * 8;
            aR = avalid ? *(const float4*)(aptr + ko) : make_float4(0, 0, 0, 0);
            bR = *(const float4*)(bptr + (size_t)ko * I_DIM);
        }
#pragma unroll
        for (int k = 0; k < 8; k++) {
            float a[8], b[8];
            *(float4*)&a[0] = *(const float4*)&As[buf][k][ty * 4];
            *(float4*)&a[4] = *(const float4*)&As[buf][k][64 + ty * 4];
            *(float4*)&b[0] = *(const float4*)&Bs[buf][k][tx * 4];
            *(float4*)&b[4] = *(const float4*)&Bs[buf][k][64 + tx * 4];
#pragma unroll
            for (int i = 0; i < 8; i++)
#pragma unroll
                for (int j = 0; j < 8; j++) acc[i][j] += a[i] * b[j];
        }
        if (kt + 1 < KT) {
            buf ^= 1;
            As[buf][acol + 0][arow] = aR.x; As[buf][acol + 1][arow] = aR.y;
            As[buf][acol + 2][arow] = aR.z; As[buf][acol + 3][arow] = aR.w;
            *(float4*)&Bs[buf][bk][bn] = bR;
            __syncthreads();
        }
    }

#pragma unroll
    for (int i = 0; i < 8; i++) {
        int r = (i < 4) ? (ty * 4 + i) : (64 + ty * 4 + i - 4);
        int mr = m0 + r;
        if (mr < ne) {
            float* crow = C + (size_t)(off + mr) * I_DIM + n0;
            *(float4*)&crow[tx * 4] = make_float4(acc[i][0], acc[i][1], acc[i][2], acc[i][3]);
            *(float4*)&crow[64 + tx * 4] = make_float4(acc[i][4], acc[i][5], acc[i][6], acc[i][7]);
        }
    }
}

// ---------------- kernel 7: hidden = silu(gate)*up*w  (in-place into g_gate) ----------------
__global__ void k_silu() {
    const size_t total4 = (size_t)PAIRS * I_DIM / 4;
    size_t stride = (size_t)gridDim.x * blockDim.x;
    for (size_t i = (size_t)blockIdx.x * blockDim.x + threadIdx.x; i < total4; i += stride) {
        float4 g = ((const float4*)g_gate)[i];
        float4 u = ((const float4*)g_up)[i];
        float w = g_pw[(i * 4) / I_DIM];
        float4 h;
        h.x = g.x / (1.0f + expf(-g.x)) * u.x * w;
        h.y = g.y / (1.0f + expf(-g.y)) * u.y * w;
        h.z = g.z / (1.0f + expf(-g.z)) * u.z * w;
        h.w = g.w / (1.0f + expf(-g.w)) * u.w * w;
        ((float4*)g_gate)[i] = h;
    }
}

// ---------------- kernel 8: SGEMM2  out[tok, :] += hidden[row, :] @ Wd[e]  ----------------
__global__ __launch_bounds__(256, 2) void k_gemm2(const float* __restrict__ Wall,
                                                  float* __restrict__ out) {
    const int e = blockIdx.z;
    const int ne = g_cnt[e];
    const int m0 = blockIdx.y * 128;
    if (m0 >= ne) return;
    const int n0 = blockIdx.x * 128;
    const int off = g_off[e];
    const float* B = Wall + (size_t)e * I_DIM * H_DIM;   // [I, H]

    __shared__ float As[2][8][132];
    __shared__ float Bs[2][8][128];

    const int tid = threadIdx.x;
    const int tx = tid & 15, ty = tid >> 4;

    const int arow = tid >> 1;
    const int acol = (tid & 1) * 4;
    const int m = m0 + arow;
    const bool avalid = (m < ne);
    const float* aptr = avalid ? (g_gate + (size_t)(off + m) * I_DIM + acol) : g_gate;

    const int bk = tid >> 5;
    const int bn = (tid & 31) * 4;
    const float* bptr = B + (size_t)bk * H_DIM + n0 + bn;

    float4 aR = avalid ? *(const float4*)aptr : make_float4(0, 0, 0, 0);
    float4 bR = *(const float4*)bptr;

    float acc[8][8];
#pragma unroll
    for (int i = 0; i < 8; i++)
#pragma unroll
        for (int j = 0; j < 8; j++) acc[i][j] = 0.0f;

    int buf = 0;
    As[0][acol + 0][arow] = aR.x; As[0][acol + 1][arow] = aR.y;
    As[0][acol + 2][arow] = aR.z; As[0][acol + 3][arow] = aR.w;
    *(float4*)&Bs[0][bk][bn] = bR;
    __syncthreads();

    const int KT = I_DIM / 8;
    for (int kt = 0; kt < KT; kt++) {
        if (kt + 1 < KT) {
            int ko = (kt + 1) * 8;
            aR = avalid ? *(const float4*)(aptr + ko) : make_float4(0, 0, 0, 0);
            bR = *(const float4*)(bptr + (size_t)ko * H_DIM);
        }
#pragma unroll
        for (int k = 0; k < 8; k++) {
            float a[8], b[8];
            *(float4*)&a[0] = *(const float4*)&As[buf][k][ty * 4];
            *(float4*)&a[4] = *(const float4*)&As[buf][k][64 + ty * 4];
            *(float4*)&b[0] = *(const float4*)&Bs[buf][k][tx * 4];
            *(float4*)&b[4] = *(const float4*)&Bs[buf][k][64 + tx * 4];
#pragma unroll
            for (int i = 0; i < 8; i++)
#pragma unroll
                for (int j = 0; j < 8; j++) acc[i][j] += a[i] * b[j];
        }
        if (kt + 1 < KT) {
            buf ^= 1;
            As[buf][acol + 0][arow] = aR.x; As[buf][acol + 1][arow] = aR.y;
            As[buf][acol + 2][arow] = aR.z; As[buf][acol + 3][arow] = aR.w;
            *(float4*)&Bs[buf][bk][bn] = bR;
            __syncthreads();
        }
    }

#pragma unroll
    for (int i = 0; i < 8; i++) {
        int r = (i < 4) ? (ty * 4 + i) : (64 + ty * 4 + i - 4);
        int mr = m0 + r;
        if (mr < ne) {
            int tok = g_ptok[off + mr];
            float* orow = out + (size_t)tok * H_DIM + n0;
#pragma unroll
            for (int j = 0; j < 4; j++) atomicAdd(&orow[tx * 4 + j], acc[i][j]);
#pragma unroll
            for (int j = 0; j < 4; j++) atomicAdd(&orow[64 + tx * 4 + j], acc[i][4 + j]);
        }
    }
}

// ---------------- launch ----------------
extern "C" void kernel_launch(void* const* d_in, const int* in_sizes, int n_in,
                              void* d_out, int out_size) {
    const float* x  = (const float*)d_in[0];
    const float* wr = (const float*)d_in[1];
    const float* wg = (const float*)d_in[2];
    const float* wu = (const float*)d_in[3];
    const float* wd = (const float*)d_in[4];
    float* out = (float*)d_out;

    k_zero<<<256, 256>>>(out);
    k_router<<<T_TOK / 8, 256>>>(x, wr);
    k_off<<<1, 32>>>();
    k_pairs<<<E_NUM, 256>>>();
    k_gemm1<<<dim3(I_DIM / 128, T_TOK / 128, E_NUM), 256>>>(x, wg, 0);
    k_gemm1<<<dim3(I_DIM / 128, T_TOK / 128, E_NUM), 256>>>(x, wu, 1);
    k_silu<<<8192, 256>>>();
    k_gemm2<<<dim3(H_DIM / 128, T_TOK / 128, E_NUM), 256>>>(wd, out);
}

// round 6
// speedup vs baseline: 1.0065x; 1.0065x over previous
#include <cuda_runtime.h>
#include <math.h>

#define T_TOK 2048
#define H_DIM 1024
#define I_DIM 2048
#define E_NUM 16
#define PAIRS (T_TOK * 2)

// ---------------- scratch (device globals; no allocations) ----------------
__device__ int   g_cnt[E_NUM];
__device__ int   g_off[E_NUM + 1];
__device__ int   g_btok[E_NUM * T_TOK];
__device__ float g_bw[E_NUM * T_TOK];
__device__ int   g_ptok[PAIRS];
__device__ float g_pw[PAIRS];
__device__ float g_gate[(size_t)PAIRS * I_DIM];   // later holds hidden = silu(g)*u*w
__device__ float g_up[(size_t)PAIRS * I_DIM];

// ---------------- kernel 1: zero output + counts ----------------
__global__ void k_zero(float* out) {
    int stride = gridDim.x * blockDim.x;
    for (int i = blockIdx.x * blockDim.x + threadIdx.x; i < T_TOK * H_DIM; i += stride)
        out[i] = 0.0f;
    if (blockIdx.x == 0 && threadIdx.x < E_NUM) g_cnt[threadIdx.x] = 0;
}

// ---------------- kernel 2: router (warp per token) ----------------
__global__ void k_router(const float* __restrict__ x, const float* __restrict__ wr) {
    int warp = (blockIdx.x * blockDim.x + threadIdx.x) >> 5;
    int lane = threadIdx.x & 31;
    if (warp >= T_TOK) return;
    const float* xr = x + (size_t)warp * H_DIM;

    float acc[E_NUM];
#pragma unroll
    for (int e = 0; e < E_NUM; e++) acc[e] = 0.0f;

    for (int h = lane; h < H_DIM; h += 32) {
        float xv = xr[h];
        const float4* w4 = (const float4*)(wr + (size_t)h * E_NUM);
#pragma unroll
        for (int q = 0; q < 4; q++) {
            float4 w = w4[q];
            acc[q * 4 + 0] += xv * w.x;
            acc[q * 4 + 1] += xv * w.y;
            acc[q * 4 + 2] += xv * w.z;
            acc[q * 4 + 3] += xv * w.w;
        }
    }
#pragma unroll
    for (int e = 0; e < E_NUM; e++) {
#pragma unroll
        for (int o = 16; o > 0; o >>= 1)
            acc[e] += __shfl_xor_sync(0xffffffffu, acc[e], o);
    }
    if (lane == 0) {
        float best = -1e30f, sec = -1e30f;
        int be = 0, se = 0;
#pragma unroll
        for (int e = 0; e < E_NUM; e++) {
            float v = acc[e];
            if (v > best) { sec = best; se = be; best = v; be = e; }
            else if (v > sec) { sec = v; se = e; }
        }
        // softmax denominator cancels when renormalizing over top-2
        float w0 = 1.0f / (1.0f + expf(sec - best));
        float w1 = 1.0f - w0;
        int p0 = atomicAdd(&g_cnt[be], 1);
        g_btok[be * T_TOK + p0] = warp;
        g_bw[be * T_TOK + p0] = w0;
        int p1 = atomicAdd(&g_cnt[se], 1);
        g_btok[se * T_TOK + p1] = warp;
        g_bw[se * T_TOK + p1] = w1;
    }
}

// ---------------- kernel 3: offsets (tiny scan over 16) ----------------
__global__ void k_off() {
    if (threadIdx.x == 0) {
        int s = 0;
        for (int e = 0; e < E_NUM; e++) { g_off[e] = s; s += g_cnt[e]; }
        g_off[E_NUM] = s;
    }
}

// ---------------- kernel 4: compact pair arrays ----------------
__global__ void k_pairs() {
    int e = blockIdx.x;
    int n = g_cnt[e], o = g_off[e];
    for (int p = threadIdx.x; p < n; p += blockDim.x) {
        g_ptok[o + p] = g_btok[e * T_TOK + p];
        g_pw[o + p]   = g_bw[e * T_TOK + p];
    }
}

// ---------------- kernel 5/6: gather SGEMM  C[row, n] = x[tok(row), :] @ W[e]
// block tile 128x128, K-tile 8, 256 threads, 8x8 microtile, double-buffered smem
__global__ __launch_bounds__(256, 2) void k_gemm1(const float* __restrict__ x,
                                                  const float* __restrict__ Wall,
                                                  int which /*0=gate,1=up*/) {
    const int e = blockIdx.z;
    const int ne = g_cnt[e];
    const int m0 = blockIdx.y * 128;
    if (m0 >= ne) return;
    const int n0 = blockIdx.x * 128;
    const int off = g_off[e];
    const float* B = Wall + (size_t)e * H_DIM * I_DIM;   // [H, I]
    float* C = which ? g_up : g_gate;

    __shared__ float As[2][8][132];
    __shared__ float Bs[2][8][128];

    const int tid = threadIdx.x;
    const int tx = tid & 15, ty = tid >> 4;

    const int arow = tid >> 1;
    const int acol = (tid & 1) * 4;
    const int m = m0 + arow;
    const bool avalid = (m < ne);
    const float* aptr = avalid ? (x + (size_t)g_ptok[off + m] * H_DIM + acol) : x;

    const int bk = tid >> 5;
    const int bn = (tid & 31) * 4;
    const float* bptr = B + (size_t)bk * I_DIM + n0 + bn;

    float4 aR = avalid ? *(const float4*)aptr : make_float4(0, 0, 0, 0);
    float4 bR = *(const float4*)bptr;

    float acc[8][8];
#pragma unroll
    for (int i = 0; i < 8; i++)
#pragma unroll
        for (int j = 0; j < 8; j++) acc[i][j] = 0.0f;

    int buf = 0;
    As[0][acol + 0][arow] = aR.x; As[0][acol + 1][arow] = aR.y;
    As[0][acol + 2][arow] = aR.z; As[0][acol + 3][arow] = aR.w;
    *(float4*)&Bs[0][bk][bn] = bR;
    __syncthreads();

    const int KT = H_DIM / 8;
    for (int kt = 0; kt < KT; kt++) {
        if (kt + 1 < KT) {
            int ko = (kt + 1) * 8;
            aR = avalid ? *(const float4*)(aptr + ko) : make_float4(0, 0, 0, 0);
            bR = *(const float4*)(bptr + (size_t)ko * I_DIM);
        }
#pragma unroll
        for (int k = 0; k < 8; k++) {
            float a[8], b[8];
            *(float4*)&a[0] = *(const float4*)&As[buf][k][ty * 4];
            *(float4*)&a[4] = *(const float4*)&As[buf][k][64 + ty * 4];
            *(float4*)&b[0] = *(const float4*)&Bs[buf][k][tx * 4];
            *(float4*)&b[4] = *(const float4*)&Bs[buf][k][64 + tx * 4];
#pragma unroll
            for (int i = 0; i < 8; i++)
#pragma unroll
                for (int j = 0; j < 8; j++) acc[i][j] += a[i] * b[j];
        }
        if (kt + 1 < KT) {
            buf ^= 1;
            As[buf][acol + 0][arow] = aR.x; As[buf][acol + 1][arow] = aR.y;
            As[buf][acol + 2][arow] = aR.z; As[buf][acol + 3][arow] = aR.w;
            *(float4*)&Bs[buf][bk][bn] = bR;
            __syncthreads();
        }
    }

#pragma unroll
    for (int i = 0; i < 8; i++) {
        int r = (i < 4) ? (ty * 4 + i) : (64 + ty * 4 + i - 4);
        int mr = m0 + r;
        if (mr < ne) {
            float* crow = C + (size_t)(off + mr) * I_DIM + n0;
            *(float4*)&crow[tx * 4] = make_float4(acc[i][0], acc[i][1], acc[i][2], acc[i][3]);
            *(float4*)&crow[64 + tx * 4] = make_float4(acc[i][4], acc[i][5], acc[i][6], acc[i][7]);
        }
    }
}

// ---------------- kernel 7: hidden = silu(gate)*up*w  (in-place into g_gate) ----------------
__global__ void k_silu() {
    const size_t total4 = (size_t)PAIRS * I_DIM / 4;
    size_t stride = (size_t)gridDim.x * blockDim.x;
    for (size_t i = (size_t)blockIdx.x * blockDim.x + threadIdx.x; i < total4; i += stride) {
        float4 g = ((const float4*)g_gate)[i];
        float4 u = ((const float4*)g_up)[i];
        float w = g_pw[(i * 4) / I_DIM];
        float4 h;
        h.x = g.x / (1.0f + expf(-g.x)) * u.x * w;
        h.y = g.y / (1.0f + expf(-g.y)) * u.y * w;
        h.z = g.z / (1.0f + expf(-g.z)) * u.z * w;
        h.w = g.w / (1.0f + expf(-g.w)) * u.w * w;
        ((float4*)g_gate)[i] = h;
    }
}

// ---------------- kernel 8: SGEMM2  out[tok, :] += hidden[row, :] @ Wd[e]  ----------------
__global__ __launch_bounds__(256, 2) void k_gemm2(const float* __restrict__ Wall,
                                                  float* __restrict__ out) {
    const int e = blockIdx.z;
    const int ne = g_cnt[e];
    const int m0 = blockIdx.y * 128;
    if (m0 >= ne) return;
    const int n0 = blockIdx.x * 128;
    const int off = g_off[e];
    const float* B = Wall + (size_t)e * I_DIM * H_DIM;   // [I, H]

    __shared__ float As[2][8][132];
    __shared__ float Bs[2][8][128];

    const int tid = threadIdx.x;
    const int tx = tid & 15, ty = tid >> 4;

    const int arow = tid >> 1;
    const int acol = (tid & 1) * 4;
    const int m = m0 + arow;
    const bool avalid = (m < ne);
    const float* aptr = avalid ? (g_gate + (size_t)(off + m) * I_DIM + acol) : g_gate;

    const int bk = tid >> 5;
    const int bn = (tid & 31) * 4;
    const float* bptr = B + (size_t)bk * H_DIM + n0 + bn;

    float4 aR = avalid ? *(const float4*)aptr : make_float4(0, 0, 0, 0);
    float4 bR = *(const float4*)bptr;

    float acc[8][8];
#pragma unroll
    for (int i = 0; i < 8; i++)
#pragma unroll
        for (int j = 0; j < 8; j++) acc[i][j] = 0.0f;

    int buf = 0;
    As[0][acol + 0][arow] = aR.x; As[0][acol + 1][arow] = aR.y;
    As[0][acol + 2][arow] = aR.z; As[0][acol + 3][arow] = aR.w;
    *(float4*)&Bs[0][bk][bn] = bR;
    __syncthreads();

    const int KT = I_DIM / 8;
    for (int kt = 0; kt < KT; kt++) {
        if (kt + 1 < KT) {
            int ko = (kt + 1) * 8;
            aR = avalid ? *(const float4*)(aptr + ko) : make_float4(0, 0, 0, 0);
            bR = *(const float4*)(bptr + (size_t)ko * H_DIM);
        }
#pragma unroll
        for (int k = 0; k < 8; k++) {
            float a[8], b[8];
            *(float4*)&a[0] = *(const float4*)&As[buf][k][ty * 4];
            *(float4*)&a[4] = *(const float4*)&As[buf][k][64 + ty * 4];
            *(float4*)&b[0] = *(const float4*)&Bs[buf][k][tx * 4];
            *(float4*)&b[4] = *(const float4*)&Bs[buf][k][64 + tx * 4];
#pragma unroll
            for (int i = 0; i < 8; i++)
#pragma unroll
                for (int j = 0; j < 8; j++) acc[i][j] += a[i] * b[j];
        }
        if (kt + 1 < KT) {
            buf ^= 1;
            As[buf][acol + 0][arow] = aR.x; As[buf][acol + 1][arow] = aR.y;
            As[buf][acol + 2][arow] = aR.z; As[buf][acol + 3][arow] = aR.w;
            *(float4*)&Bs[buf][bk][bn] = bR;
            __syncthreads();
        }
    }

#pragma unroll
    for (int i = 0; i < 8; i++) {
        int r = (i < 4) ? (ty * 4 + i) : (64 + ty * 4 + i - 4);
        int mr = m0 + r;
        if (mr < ne) {
            int tok = g_ptok[off + mr];
            float* orow = out + (size_t)tok * H_DIM + n0;
#pragma unroll
            for (int j = 0; j < 4; j++) atomicAdd(&orow[tx * 4 + j], acc[i][j]);
#pragma unroll
            for (int j = 0; j < 4; j++) atomicAdd(&orow[64 + tx * 4 + j], acc[i][4 + j]);
        }
    }
}

// ---------------- launch ----------------
extern "C" void kernel_launch(void* const* d_in, const int* in_sizes, int n_in,
                              void* d_out, int out_size) {
    const float* x  = (const float*)d_in[0];
    const float* wr = (const float*)d_in[1];
    const float* wg = (const float*)d_in[2];
    const float* wu = (const float*)d_in[3];
    const float* wd = (const float*)d_in[4];
    float* out = (float*)d_out;

    k_zero<<<256, 256>>>(out);
    k_router<<<T_TOK / 8, 256>>>(x, wr);
    k_off<<<1, 32>>>();
    k_pairs<<<E_NUM, 256>>>();
    k_gemm1<<<dim3(I_DIM / 128, T_TOK / 128, E_NUM), 256>>>(x, wg, 0);
    k_gemm1<<<dim3(I_DIM / 128, T_TOK / 128, E_NUM), 256>>>(x, wu, 1);
    k_silu<<<8192, 256>>>();
    k_gemm2<<<dim3(H_DIM / 128, T_TOK / 128, E_NUM), 256>>>(wd, out);
}

// round 7
// speedup vs baseline: 1.0363x; 1.0296x over previous
#include <cuda_runtime.h>
#include <math.h>

#define T_TOK 2048
#define H_DIM 1024
#define I_DIM 2048
#define E_NUM 16
#define PAIRS (T_TOK * 2)

// ---------------- scratch (device globals; no allocations) ----------------
__device__ int   g_cnt[E_NUM];
__device__ int   g_off[E_NUM + 1];
__device__ int   g_btok[E_NUM * T_TOK];
__device__ float g_bw[E_NUM * T_TOK];
__device__ int   g_ptok[PAIRS];
__device__ float g_pw[PAIRS];
__device__ float g_gate[(size_t)PAIRS * I_DIM];   // later holds hidden = silu(g)*u*w
__device__ float g_up[(size_t)PAIRS * I_DIM];

// ---------------- kernel 1: zero output + counts ----------------
__global__ void k_zero(float* out) {
    int stride = gridDim.x * blockDim.x;
    for (int i = blockIdx.x * blockDim.x + threadIdx.x; i < T_TOK * H_DIM; i += stride)
        out[i] = 0.0f;
    if (blockIdx.x == 0 && threadIdx.x < E_NUM) g_cnt[threadIdx.x] = 0;
}

// ---------------- kernel 2: router (warp per token) ----------------
__global__ void k_router(const float* __restrict__ x, const float* __restrict__ wr) {
    int warp = (blockIdx.x * blockDim.x + threadIdx.x) >> 5;
    int lane = threadIdx.x & 31;
    if (warp >= T_TOK) return;
    const float* xr = x + (size_t)warp * H_DIM;

    float acc[E_NUM];
#pragma unroll
    for (int e = 0; e < E_NUM; e++) acc[e] = 0.0f;

    for (int h = lane; h < H_DIM; h += 32) {
        float xv = xr[h];
        const float4* w4 = (const float4*)(wr + (size_t)h * E_NUM);
#pragma unroll
        for (int q = 0; q < 4; q++) {
            float4 w = w4[q];
            acc[q * 4 + 0] += xv * w.x;
            acc[q * 4 + 1] += xv * w.y;
            acc[q * 4 + 2] += xv * w.z;
            acc[q * 4 + 3] += xv * w.w;
        }
    }
#pragma unroll
    for (int e = 0; e < E_NUM; e++) {
#pragma unroll
        for (int o = 16; o > 0; o >>= 1)
            acc[e] += __shfl_xor_sync(0xffffffffu, acc[e], o);
    }
    if (lane == 0) {
        float best = -1e30f, sec = -1e30f;
        int be = 0, se = 0;
#pragma unroll
        for (int e = 0; e < E_NUM; e++) {
            float v = acc[e];
            if (v > best) { sec = best; se = be; best = v; be = e; }
            else if (v > sec) { sec = v; se = e; }
        }
        // softmax denominator cancels when renormalizing over top-2
        float w0 = 1.0f / (1.0f + expf(sec - best));
        float w1 = 1.0f - w0;
        int p0 = atomicAdd(&g_cnt[be], 1);
        g_btok[be * T_TOK + p0] = warp;
        g_bw[be * T_TOK + p0] = w0;
        int p1 = atomicAdd(&g_cnt[se], 1);
        g_btok[se * T_TOK + p1] = warp;
        g_bw[se * T_TOK + p1] = w1;
    }
}

// ---------------- kernel 3: offsets (tiny scan over 16) ----------------
__global__ void k_off() {
    if (threadIdx.x == 0) {
        int s = 0;
        for (int e = 0; e < E_NUM; e++) { g_off[e] = s; s += g_cnt[e]; }
        g_off[E_NUM] = s;
    }
}

// ---------------- kernel 4: compact pair arrays ----------------
__global__ void k_pairs() {
    int e = blockIdx.x;
    int n = g_cnt[e], o = g_off[e];
    for (int p = threadIdx.x; p < n; p += blockDim.x) {
        g_ptok[o + p] = g_btok[e * T_TOK + p];
        g_pw[o + p]   = g_bw[e * T_TOK + p];
    }
}

// ---------------- kernel 5/6: gather SGEMM  C[row, n] = x[tok(row), :] @ W[e]
// block tile 128x128, K-tile 8, 256 threads, 8x8 microtile, double-buffered smem
__global__ __launch_bounds__(256, 2) void k_gemm1(const float* __restrict__ x,
                                                  const float* __restrict__ Wall,
                                                  int which /*0=gate,1=up*/) {
    const int e = blockIdx.z;
    const int ne = g_cnt[e];
    const int m0 = blockIdx.y * 128;
    if (m0 >= ne) return;
    const int n0 = blockIdx.x * 128;
    const int off = g_off[e];
    const float* B = Wall + (size_t)e * H_DIM * I_DIM;   // [H, I]
    float* C = which ? g_up : g_gate;

    __shared__ float As[2][8][132];
    __shared__ float Bs[2][8][128];

    const int tid = threadIdx.x;
    const int tx = tid & 15, ty = tid >> 4;

    const int arow = tid >> 1;
    const int acol = (tid & 1) * 4;
    const int m = m0 + arow;
    const bool avalid = (m < ne);
    const float* aptr = avalid ? (x + (size_t)g_ptok[off + m] * H_DIM + acol) : x;

    const int bk = tid >> 5;
    const int bn = (tid & 31) * 4;
    const float* bptr = B + (size_t)bk * I_DIM + n0 + bn;

    float4 aR = avalid ? *(const float4*)aptr : make_float4(0, 0, 0, 0);
    float4 bR = *(const float4*)bptr;

    float acc[8][8];
#pragma unroll
    for (int i = 0; i < 8; i++)
#pragma unroll
        for (int j = 0; j < 8; j++) acc[i][j] = 0.0f;

    int buf = 0;
    As[0][acol + 0][arow] = aR.x; As[0][acol + 1][arow] = aR.y;
    As[0][acol + 2][arow] = aR.z; As[0][acol + 3][arow] = aR.w;
    *(float4*)&Bs[0][bk][bn] = bR;
    __syncthreads();

    const int KT = H_DIM / 8;
    for (int kt = 0; kt < KT; kt++) {
        if (kt + 1 < KT) {
            int ko = (kt + 1) * 8;
            aR = avalid ? *(const float4*)(aptr + ko) : make_float4(0, 0, 0, 0);
            bR = *(const float4*)(bptr + (size_t)ko * I_DIM);
        }
#pragma unroll
        for (int k = 0; k < 8; k++) {
            float a[8], b[8];
            *(float4*)&a[0] = *(const float4*)&As[buf][k][ty * 4];
            *(float4*)&a[4] = *(const float4*)&As[buf][k][64 + ty * 4];
            *(float4*)&b[0] = *(const float4*)&Bs[buf][k][tx * 4];
            *(float4*)&b[4] = *(const float4*)&Bs[buf][k][64 + tx * 4];
#pragma unroll
            for (int i = 0; i < 8; i++)
#pragma unroll
                for (int j = 0; j < 8; j++) acc[i][j] += a[i] * b[j];
        }
        if (kt + 1 < KT) {
            buf ^= 1;
            As[buf][acol + 0][arow] = aR.x; As[buf][acol + 1][arow] = aR.y;
            As[buf][acol + 2][arow] = aR.z; As[buf][acol + 3][arow] = aR.w;
            *(float4*)&Bs[buf][bk][bn] = bR;
            __syncthreads();
        }
    }

#pragma unroll
    for (int i = 0; i < 8; i++) {
        int r = (i < 4) ? (ty * 4 + i) : (64 + ty * 4 + i - 4);
        int mr = m0 + r;
        if (mr < ne) {
            float* crow = C + (size_t)(off + mr) * I_DIM + n0;
            *(float4*)&crow[tx * 4] = make_float4(acc[i][0], acc[i][1], acc[i][2], acc[i][3]);
            *(float4*)&crow[64 + tx * 4] = make_float4(acc[i][4], acc[i][5], acc[i][6], acc[i][7]);
        }
    }
}

// ---------------- kernel 7: hidden = silu(gate)*up*w  (in-place into g_gate) ----------------
__global__ void k_silu() {
    const size_t total4 = (size_t)PAIRS * I_DIM / 4;
    size_t stride = (size_t)gridDim.x * blockDim.x;
    for (size_t i = (size_t)blockIdx.x * blockDim.x + threadIdx.x; i < total4; i += stride) {
        float4 g = ((const float4*)g_gate)[i];
        float4 u = ((const float4*)g_up)[i];
        float w = g_pw[(i * 4) / I_DIM];
        float4 h;
        h.x = g.x / (1.0f + expf(-g.x)) * u.x * w;
        h.y = g.y / (1.0f + expf(-g.y)) * u.y * w;
        h.z = g.z / (1.0f + expf(-g.z)) * u.z * w;
        h.w = g.w / (1.0f + expf(-g.w)) * u.w * w;
        ((float4*)g_gate)[i] = h;
    }
}

// ---------------- kernel 8: SGEMM2  out[tok, :] += hidden[row, :] @ Wd[e]  ----------------
__global__ __launch_bounds__(256, 2) void k_gemm2(const float* __restrict__ Wall,
                                                  float* __restrict__ out) {
    const int e = blockIdx.z;
    const int ne = g_cnt[e];
    const int m0 = blockIdx.y * 128;
    if (m0 >= ne) return;
    const int n0 = blockIdx.x * 128;
    const int off = g_off[e];
    const float* B = Wall + (size_t)e * I_DIM * H_DIM;   // [I, H]

    __shared__ float As[2][8][132];
    __shared__ float Bs[2][8][128];

    const int tid = threadIdx.x;
    const int tx = tid & 15, ty = tid >> 4;

    const int arow = tid >> 1;
    const int acol = (tid & 1) * 4;
    const int m = m0 + arow;
    const bool avalid = (m < ne);
    const float* aptr = avalid ? (g_gate + (size_t)(off + m) * I_DIM + acol) : g_gate;

    const int bk = tid >> 5;
    const int bn = (tid & 31) * 4;
    const float* bptr = B + (size_t)bk * H_DIM + n0 + bn;

    float4 aR = avalid ? *(const float4*)aptr : make_float4(0, 0, 0, 0);
    float4 bR = *(const float4*)bptr;

    float acc[8][8];
#pragma unroll
    for (int i = 0; i < 8; i++)
#pragma unroll
        for (int j = 0; j < 8; j++) acc[i][j] = 0.0f;

    int buf = 0;
    As[0][acol + 0][arow] = aR.x; As[0][acol + 1][arow] = aR.y;
    As[0][acol + 2][arow] = aR.z; As[0][acol + 3][arow] = aR.w;
    *(float4*)&Bs[0][bk][bn] = bR;
    __syncthreads();

    const int KT = I_DIM / 8;
    for (int kt = 0; kt < KT; kt++) {
        if (kt + 1 < KT) {
            int ko = (kt + 1) * 8;
            aR = avalid ? *(const float4*)(aptr + ko) : make_float4(0, 0, 0, 0);
            bR = *(const float4*)(bptr + (size_t)ko * H_DIM);
        }
#pragma unroll
        for (int k = 0; k < 8; k++) {
            float a[8], b[8];
            *(float4*)&a[0] = *(const float4*)&As[buf][k][ty * 4];
            *(float4*)&a[4] = *(const float4*)&As[buf][k][64 + ty * 4];
            *(float4*)&b[0] = *(const float4*)&Bs[buf][k][tx * 4];
            *(float4*)&b[4] = *(const float4*)&Bs[buf][k][64 + tx * 4];
#pragma unroll
            for (int i = 0; i < 8; i++)
#pragma unroll
                for (int j = 0; j < 8; j++) acc[i][j] += a[i] * b[j];
        }
        if (kt + 1 < KT) {
            buf ^= 1;
            As[buf][acol + 0][arow] = aR.x; As[buf][acol + 1][arow] = aR.y;
            As[buf][acol + 2][arow] = aR.z; As[buf][acol + 3][arow] = aR.w;
            *(float4*)&Bs[buf][bk][bn] = bR;
            __syncthreads();
        }
    }

#pragma unroll
    for (int i = 0; i < 8; i++) {
        int r = (i < 4) ? (ty * 4 + i) : (64 + ty * 4 + i - 4);
        int mr = m0 + r;
        if (mr < ne) {
            int tok = g_ptok[off + mr];
            float* orow = out + (size_t)tok * H_DIM + n0;
#pragma unroll
            for (int j = 0; j < 4; j++) atomicAdd(&orow[tx * 4 + j], acc[i][j]);
#pragma unroll
            for (int j = 0; j < 4; j++) atomicAdd(&orow[64 + tx * 4 + j], acc[i][4 + j]);
        }
    }
}

// ---------------- launch ----------------
extern "C" void kernel_launch(void* const* d_in, const int* in_sizes, int n_in,
                              void* d_out, int out_size) {
    const float* x  = (const float*)d_in[0];
    const float* wr = (const float*)d_in[1];
    const float* wg = (const float*)d_in[2];
    const float* wu = (const float*)d_in[3];
    const float* wd = (const float*)d_in[4];
    float* out = (float*)d_out;

    k_zero<<<256, 256>>>(out);
    k_router<<<T_TOK / 8, 256>>>(x, wr);
    k_off<<<1, 32>>>();
    k_pairs<<<E_NUM, 256>>>();
    k_gemm1<<<dim3(I_DIM / 128, T_TOK / 128, E_NUM), 256>>>(x, wg, 0);
    k_gemm1<<<dim3(I_DIM / 128, T_TOK / 128, E_NUM), 256>>>(x, wu, 1);
    k_silu<<<8192, 256>>>();
    k_gemm2<<<dim3(H_DIM / 128, T_TOK / 128, E_NUM), 256>>>(wd, out);
}